// round 10
// baseline (speedup 1.0000x reference)
#include <cuda_runtime.h>
#include <math.h>

// ---------------- problem constants ----------------
#define NB 32
#define NS 128
#define ND 300
#define NVOC 20000
#define NK 8
#define MROWS 4096           // NB*NS
#define LDA 304              // D padded to mult of 8
#define NV1 20001            // VOCAB + default col
#define EW 20096             // padded logits width = 157*128
#define NT1 157              // n-tiles for GEMM1
#define LDWB 384             // padded N width for W / vocab-as-B (3 tiles of 128)
#define LDJ 1280             // padded N width for WihT (10 tiles of 128)
#define NG 1200              // 4*D
#define NSPLIT 8
#define KCH 2560             // split-K chunk (mult of 8); last split gets 2080
#define RCTAS 150            // persistent recurrent CTAs (2 hidden units each)
#define HSZ (ND*NB)          // 9600 floats; h layout [d*32 + b]

// ---------------- device scratch (zero-initialized at module load) ----------------
__device__ float g_Xw[MROWS*LDA];                    // padded words
__device__ float g_X [MROWS*LDA];                    // words @ W (padded cols stay 0)
__device__ float g_Wp[LDA*LDWB];                     // padded W
__device__ float g_CT[LDA*EW];                       // [k][v] = vocab[v][k]; col 20000 = default_embed
__device__ float g_E [(size_t)MROWS*EW];             // exp(logits), unnormalized (~329MB)
__device__ float g_part[NT1*MROWS];                  // per-n-tile row sums
__device__ float g_Z[MROWS];                         // softmax denominators
__device__ float g_Vbp[(size_t)NVOC*LDWB];           // padded vocab as B operand
__device__ float g_Vp[(size_t)NSPLIT*MROWS*LDA];     // split-K partials of E@vocab
__device__ float g_V [MROWS*LDA];                    // mixed embeddings (normalized), padded cols 0
__device__ float g_WihT[LDA*LDJ];                    // lstm_Wih transposed, padded
__device__ float g_bsum[NG];                         // lstm_bih + lstm_bhh
__device__ float g_G[(size_t)NG*MROWS];              // LSTM input preacts, layout [j][t*32+b]
__device__ float g_h[2*HSZ];                         // LSTM h double buffer, [d*32+b]
__device__ float g_rh[2*HSZ];                        // RNN h double buffer
__device__ float g_H[NB*NK*ND];                      // RNN outputs [b][k][d]
__device__ unsigned g_cnt;
__device__ unsigned g_gen;

// ---------------- builder kernels (grid-stride) ----------------
__global__ void k_pad_words(const float* __restrict__ words) {
    const int total = MROWS*LDA;
    for (int i = blockIdx.x*blockDim.x + threadIdx.x; i < total; i += gridDim.x*blockDim.x) {
        int m = i / LDA, n = i - m*LDA;
        g_Xw[i] = (n < ND) ? words[m*ND + n] : 0.f;
    }
}
__global__ void k_build_wp(const float* __restrict__ W) {
    const int total = LDA*LDWB;
    for (int i = blockIdx.x*blockDim.x + threadIdx.x; i < total; i += gridDim.x*blockDim.x) {
        int k = i / LDWB, n = i - k*LDWB;
        g_Wp[i] = (k < ND && n < ND) ? W[k*ND + n] : 0.f;
    }
}
__global__ void k_build_ct(const float* __restrict__ vocab, const float* __restrict__ de) {
    const int total = LDA*EW;
    for (int i = blockIdx.x*blockDim.x + threadIdx.x; i < total; i += gridDim.x*blockDim.x) {
        int k = i / EW, v = i - k*EW;
        float val = 0.f;
        if (k < ND) {
            if (v < NVOC)       val = vocab[(size_t)v*ND + k];
            else if (v == NVOC) val = de[k];
        }
        g_CT[i] = val;
    }
}
__global__ void k_build_vb(const float* __restrict__ vocab) {
    const size_t total = (size_t)NVOC*LDWB;
    for (size_t i = blockIdx.x*(size_t)blockDim.x + threadIdx.x; i < total; i += gridDim.x*(size_t)blockDim.x) {
        size_t v = i / LDWB; int n = (int)(i - v*LDWB);
        g_Vbp[i] = (n < ND) ? vocab[v*ND + n] : 0.f;
    }
}
__global__ void k_build_wih(const float* __restrict__ Wih) {
    const int total = LDA*LDJ;
    for (int i = blockIdx.x*blockDim.x + threadIdx.x; i < total; i += gridDim.x*blockDim.x) {
        int k = i / LDJ, j = i - k*LDJ;
        g_WihT[i] = (k < ND && j < NG) ? Wih[(size_t)j*ND + k] : 0.f;
    }
}
__global__ void k_bsum(const float* __restrict__ bih, const float* __restrict__ bhh) {
    int i = blockIdx.x*blockDim.x + threadIdx.x;
    if (i < NG) g_bsum[i] = bih[i] + bhh[i];
}

// ---------------- shared SGEMM core: 128x128 tile, BK=8, 256 threads, 8x8 micro ----------------
__device__ __forceinline__ void gemm_core(const float* __restrict__ A, int lda,
                                          const float* __restrict__ B, int ldb,
                                          int kBeg, int kEnd, int mBase, int nBase,
                                          float (&acc)[8][8])
{
    __shared__ float sA[8][128];
    __shared__ float sB[8][128];
    const int tid  = threadIdx.x;
    const int tx   = tid & 15, ty = tid >> 4;
    const int aRow = tid >> 1, aCol = (tid & 1) << 2;
    const int bRow = tid >> 5, bCol = (tid & 31) << 2;
    const float* Aptr = A + (size_t)(mBase + aRow)*lda + aCol;
    const float* Bptr = B + (size_t)bRow*ldb + nBase + bCol;

    for (int k0 = kBeg; k0 < kEnd; k0 += 8) {
        float4 av = *(const float4*)(Aptr + k0);
        float4 bv = *(const float4*)(Bptr + (size_t)k0*ldb);
        __syncthreads();
        sA[aCol+0][aRow] = av.x; sA[aCol+1][aRow] = av.y;
        sA[aCol+2][aRow] = av.z; sA[aCol+3][aRow] = av.w;
        *(float4*)&sB[bRow][bCol] = bv;
        __syncthreads();
        #pragma unroll
        for (int kk = 0; kk < 8; kk++) {
            float ar[8], br[8];
            *(float4*)&ar[0] = *(const float4*)&sA[kk][ty*8];
            *(float4*)&ar[4] = *(const float4*)&sA[kk][ty*8+4];
            *(float4*)&br[0] = *(const float4*)&sB[kk][tx*8];
            *(float4*)&br[4] = *(const float4*)&sB[kk][tx*8+4];
            #pragma unroll
            for (int i = 0; i < 8; i++)
                #pragma unroll
                for (int j = 0; j < 8; j++)
                    acc[i][j] += ar[i]*br[j];
        }
    }
}

// GEMM0: X = Xw @ Wp  (M=4096, N=300, K=304)
__global__ void k_gemm0() {
    float acc[8][8] = {};
    int nBase = blockIdx.x*128, mBase = blockIdx.y*128;
    gemm_core(g_Xw, LDA, g_Wp, LDWB, 0, LDA, mBase, nBase, acc);
    int tx = threadIdx.x & 15, ty = threadIdx.x >> 4;
    #pragma unroll
    for (int i = 0; i < 8; i++) {
        int r = mBase + ty*8 + i;
        #pragma unroll
        for (int j = 0; j < 8; j++) {
            int c = nBase + tx*8 + j;
            if (c < ND) g_X[(size_t)r*LDA + c] = acc[i][j];
        }
    }
}

// GEMM1: E = exp(X @ CT) + per-tile row sums  (M=4096, N=20096, K=304)
__global__ void k_gemm1() {
    float acc[8][8] = {};
    int nBase = blockIdx.x*128, mBase = blockIdx.y*128;
    gemm_core(g_X, LDA, g_CT, EW, 0, LDA, mBase, nBase, acc);
    int tx = threadIdx.x & 15, ty = threadIdx.x >> 4;
    #pragma unroll
    for (int i = 0; i < 8; i++) {
        int r = mBase + ty*8 + i;
        float s = 0.f;
        #pragma unroll
        for (int j = 0; j < 8; j++) {
            int c = nBase + tx*8 + j;
            float e = (c < NV1) ? expf(acc[i][j]) : 0.f;
            g_E[(size_t)r*EW + c] = e;
            s += e;
        }
        // reduce across the 16 tx lanes (contiguous within the warp)
        #pragma unroll
        for (int off = 8; off >= 1; off >>= 1)
            s += __shfl_down_sync(0xffffffffu, s, off, 16);
        if (tx == 0) g_part[(size_t)blockIdx.x*MROWS + r] = s;
    }
}

__global__ void k_zred() {
    int m = blockIdx.x*blockDim.x + threadIdx.x;
    if (m < MROWS) {
        float s = 0.f;
        for (int i = 0; i < NT1; i++) s += g_part[(size_t)i*MROWS + m];
        g_Z[m] = s;
    }
}

// GEMM2: Vp[split] = E[:, split-range] @ Vbp  (split-K, M=4096, N=300(384), K=20000)
__global__ void k_gemm2() {
    float acc[8][8] = {};
    int nBase = blockIdx.x*128, mBase = blockIdx.y*128;
    int split = blockIdx.z;
    int kBeg = split*KCH;
    int kEnd = kBeg + KCH; if (kEnd > NVOC) kEnd = NVOC;
    gemm_core(g_E, EW, g_Vbp, LDWB, kBeg, kEnd, mBase, nBase, acc);
    int tx = threadIdx.x & 15, ty = threadIdx.x >> 4;
    #pragma unroll
    for (int i = 0; i < 8; i++) {
        int r = mBase + ty*8 + i;
        #pragma unroll
        for (int j = 0; j < 8; j++) {
            int c = nBase + tx*8 + j;
            if (c < ND) g_Vp[((size_t)split*MROWS + r)*LDA + c] = acc[i][j];
        }
    }
}

// V = (sum_splits Vp + E[:,20000]*words) / Z
__global__ void k_vfinal() {
    int i = blockIdx.x*blockDim.x + threadIdx.x;
    if (i >= MROWS*ND) return;
    int m = i / ND, n = i - m*ND;
    float s = 0.f;
    #pragma unroll
    for (int sp = 0; sp < NSPLIT; sp++) s += g_Vp[((size_t)sp*MROWS + m)*LDA + n];
    float pdef = g_E[(size_t)m*EW + NVOC];
    g_V[(size_t)m*LDA + n] = (s + pdef * g_Xw[(size_t)m*LDA + n]) / g_Z[m];
}

// GEMM3: G = V @ WihT + bsum, output layout [j][t*32+b]  (M=4096, N=1200(1280), K=304)
__global__ void k_gemm3() {
    float acc[8][8] = {};
    int nBase = blockIdx.x*128, mBase = blockIdx.y*128;
    gemm_core(g_V, LDA, g_WihT, LDJ, 0, LDA, mBase, nBase, acc);
    int tx = threadIdx.x & 15, ty = threadIdx.x >> 4;
    #pragma unroll
    for (int i = 0; i < 8; i++) {
        int r = mBase + ty*8 + i;          // r = b*128 + t
        int b = r >> 7, t = r & 127;
        #pragma unroll
        for (int j = 0; j < 8; j++) {
            int c = nBase + tx*8 + j;
            if (c < NG) g_G[(size_t)c*MROWS + t*32 + b] = acc[i][j] + g_bsum[c];
        }
    }
}

// ---------------- persistent recurrent kernel: LSTM (128 steps) + RNN (8 steps) ----------------
__device__ __forceinline__ void gridbar() {
    __syncthreads();
    if (threadIdx.x == 0) {
        __threadfence();
        unsigned g = *(volatile unsigned*)&g_gen;
        unsigned arrived = atomicAdd(&g_cnt, 1u);
        if (arrived == RCTAS - 1) {
            atomicExch(&g_cnt, 0u);
            __threadfence();
            atomicAdd(&g_gen, 1u);
        } else {
            volatile unsigned* vg = &g_gen;
            while (*vg == g) __nanosleep(64);
        }
        __threadfence();
    }
    __syncthreads();
}

__global__ void __launch_bounds__(256, 8) k_recur(
    const float* __restrict__ lWhh, const float* __restrict__ rWih,
    const float* __restrict__ rWhh, const float* __restrict__ rbih,
    const float* __restrict__ rbhh, const int* __restrict__ lengths)
{
    __shared__ float sW[8][300];     // lstm_Whh rows for (4 gates x 2 units)
    __shared__ float sWi[2][300];    // rnn_Wih rows
    __shared__ float sWr[2][300];    // rnn_Whh rows
    __shared__ float sC[2][32];      // cell state
    __shared__ float sGate[4][64];
    __shared__ float sRed[4][64];
    __shared__ float sA[64];         // rnn fixed preact

    const int tid = threadIdx.x;
    const int q = tid >> 6, dl = (tid >> 5) & 1, b = tid & 31;
    const int d0 = blockIdx.x * 2;
    const int d = d0 + dl;

    // stage weight rows (fixed across steps)
    for (int i = tid; i < 8*300; i += 256) {
        int r = i / 300, k = i - r*300;
        sW[r][k] = lWhh[((size_t)((r >> 1)*ND + d0 + (r & 1)))*ND + k];
    }
    for (int i = tid; i < 600; i += 256) {
        int r = i / 300, k = i - r*300;
        sWi[r][k] = rWih[(size_t)(d0 + r)*ND + k];
        sWr[r][k] = rWhh[(size_t)(d0 + r)*ND + k];
    }
    if (q == 0) { sC[dl][b] = 0.f; g_h[d*32 + b] = 0.f; }   // h buffer 0 init
    gridbar();

    const int len = lengths[b];
    const int wrow = q*2 + dl;

    // ---- LSTM over time ----
    for (int st = 0; st < NS; st++) {
        const float* hc = g_h + (st & 1)*HSZ;
        float acc = 0.f;
        #pragma unroll 5
        for (int k = 0; k < 300; k++)
            acc += sW[wrow][k] * __ldcg(&hc[k*32 + b]);
        acc += g_G[(size_t)(q*ND + d)*MROWS + st*32 + b];
        sGate[q][dl*32 + b] = acc;
        __syncthreads();
        if (q == 0) {
            float gi = sGate[0][dl*32+b], gf = sGate[1][dl*32+b];
            float gg = sGate[2][dl*32+b], go = sGate[3][dl*32+b];
            float si = 1.f/(1.f + expf(-gi));
            float sf = 1.f/(1.f + expf(-gf));
            float so = 1.f/(1.f + expf(-go));
            float cn = sf*sC[dl][b] + si*tanhf(gg);
            float hn = so*tanhf(cn);
            float* hx = g_h + ((st + 1) & 1)*HSZ;
            if (st < len) { sC[dl][b] = cn; __stcg(&hx[d*32 + b], hn); }
            else          { __stcg(&hx[d*32 + b], __ldcg(&hc[d*32 + b])); }
        }
        gridbar();
    }

    // ---- RNN fixed preact: A = q_final @ rWih^T + rbih + rbhh ----
    const float* qf = g_h;   // after 128 steps, final h is in buffer 0
    {
        int k0 = q * 75;
        float pa = 0.f;
        #pragma unroll 5
        for (int k = k0; k < k0 + 75; k++)
            pa += sWi[dl][k] * __ldcg(&qf[k*32 + b]);
        sRed[q][dl*32 + b] = pa;
        __syncthreads();
        if (q == 0) {
            float s = sRed[0][dl*32+b] + sRed[1][dl*32+b] + sRed[2][dl*32+b] + sRed[3][dl*32+b];
            sA[dl*32 + b] = s + rbih[d] + rbhh[d];
            g_rh[d*32 + b] = 0.f;   // rnn h buffer 0 init
        }
        gridbar();
    }

    // ---- RNN K steps ----
    for (int kk = 0; kk < NK; kk++) {
        const float* rc = g_rh + (kk & 1)*HSZ;
        int k0 = q * 75;
        float pa = 0.f;
        #pragma unroll 5
        for (int k = k0; k < k0 + 75; k++)
            pa += sWr[dl][k] * __ldcg(&rc[k*32 + b]);
        sRed[q][dl*32 + b] = pa;
        __syncthreads();
        if (q == 0) {
            float s = sRed[0][dl*32+b] + sRed[1][dl*32+b] + sRed[2][dl*32+b] + sRed[3][dl*32+b];
            float h2 = tanhf(sA[dl*32 + b] + s);
            __stcg(&g_rh[((kk + 1) & 1)*HSZ + d*32 + b], h2);
            g_H[(size_t)(b*NK + kk)*ND + d] = h2;
        }
        gridbar();
    }
}

// ---------------- attention: one CTA per (b, k) ----------------
__global__ void k_attn(const int* __restrict__ lengths, float* __restrict__ out) {
    int bk = blockIdx.x;
    int b = bk >> 3, kk = bk & 7;
    __shared__ float sH[300];
    __shared__ float sP[128];
    __shared__ float sWr1[4], sWr2[4];
    int tid = threadIdx.x;   // 128 threads

    for (int dd = tid; dd < ND; dd += 128) sH[dd] = g_H[(size_t)(b*NK + kk)*ND + dd];
    __syncthreads();

    int len = lengths[b];
    float sc;
    {
        const float* vrow = &g_V[(size_t)(b*NS + tid)*LDA];
        float a = 0.f;
        #pragma unroll 4
        for (int dd = 0; dd < ND; dd++) a += sH[dd]*vrow[dd];
        sc = (tid < len) ? a : -1e30f;
    }
    // block max (4 warps)
    float m = sc;
    #pragma unroll
    for (int off = 16; off; off >>= 1) m = fmaxf(m, __shfl_xor_sync(0xffffffffu, m, off));
    if ((tid & 31) == 0) sWr1[tid >> 5] = m;
    __syncthreads();
    float mx = fmaxf(fmaxf(sWr1[0], sWr1[1]), fmaxf(sWr1[2], sWr1[3]));
    float e = expf(sc - mx);
    float s = e;
    #pragma unroll
    for (int off = 16; off; off >>= 1) s += __shfl_xor_sync(0xffffffffu, s, off);
    if ((tid & 31) == 0) sWr2[tid >> 5] = s;
    __syncthreads();
    float sum = sWr2[0] + sWr2[1] + sWr2[2] + sWr2[3];
    sP[tid] = e / sum;
    __syncthreads();

    for (int dd = tid; dd < ND; dd += 128) {
        float r = 0.f;
        #pragma unroll 4
        for (int ss = 0; ss < NS; ss++) r += sP[ss] * g_V[(size_t)(b*NS + ss)*LDA + dd];
        out[(size_t)(b*NK + kk)*ND + dd] = r;
    }
}

// ---------------- launch ----------------
extern "C" void kernel_launch(void* const* d_in, const int* in_sizes, int n_in,
                              void* d_out, int out_size) {
    const float* words = (const float*)d_in[0];
    const int*   lens  = (const int*)  d_in[1];
    const float* vocab = (const float*)d_in[2];
    const float* de    = (const float*)d_in[3];
    const float* W     = (const float*)d_in[4];
    const float* lWih  = (const float*)d_in[5];
    const float* lWhh  = (const float*)d_in[6];
    const float* lbih  = (const float*)d_in[7];
    const float* lbhh  = (const float*)d_in[8];
    const float* rWih  = (const float*)d_in[9];
    const float* rWhh  = (const float*)d_in[10];
    const float* rbih  = (const float*)d_in[11];
    const float* rbhh  = (const float*)d_in[12];
    float* out = (float*)d_out;

    k_pad_words<<<1024, 256>>>(words);
    k_build_wp <<<64,   256>>>(W);
    k_build_ct <<<2048, 256>>>(vocab, de);
    k_build_vb <<<2048, 256>>>(vocab);
    k_build_wih<<<256,  256>>>(lWih);
    k_bsum     <<<8,    256>>>(lbih, lbhh);

    k_gemm0<<<dim3(3, 32), 256>>>();
    k_gemm1<<<dim3(NT1, 32), 256>>>();
    k_zred <<<16, 256>>>();
    k_gemm2<<<dim3(3, 32, NSPLIT), 256>>>();
    k_vfinal<<<(MROWS*ND + 255)/256, 256>>>();
    k_gemm3<<<dim3(10, 32), 256>>>();

    k_recur<<<RCTAS, 256>>>(lWhh, rWih, rWhh, rbih, rbhh, lens);
    k_attn <<<NB*NK, 128>>>(lens, out);
}